// round 5
// baseline (speedup 1.0000x reference)
#include <cuda_runtime.h>
#include <cuda_bf16.h>
#include <cstdint>

#define NLOC  384
#define DHID  32
#define DPAIR 64
#define NCOL  (NLOC * DPAIR)   // 24576

// ---------------- scratch (static device globals; no allocations) ----------
__device__ __align__(16) __nv_bfloat16 g_Ah[NLOC * DHID];  // a hi  [384][32]
__device__ __align__(16) __nv_bfloat16 g_Al[NLOC * DHID];  // a lo  [384][32]
__device__ __align__(16) __nv_bfloat16 g_Ch[NCOL * DHID];  // C hi  [24576][32]
__device__ __align__(16) __nv_bfloat16 g_Cl[NCOL * DHID];  // C lo  [24576][32]

// ---------------- mma.sync / ldmatrix helpers -------------------------------
__device__ __forceinline__ uint32_t smem_u32(const void* p) {
    uint32_t a;
    asm("{ .reg .u64 t; cvta.to.shared.u64 t, %1; cvt.u32.u64 %0, t; }"
        : "=r"(a) : "l"(p));
    return a;
}
__device__ __forceinline__ void ldsm_x4(uint32_t* r, uint32_t addr) {
    asm volatile("ldmatrix.sync.aligned.m8n8.x4.shared.b16 {%0,%1,%2,%3}, [%4];"
                 : "=r"(r[0]), "=r"(r[1]), "=r"(r[2]), "=r"(r[3]) : "r"(addr));
}
__device__ __forceinline__ void mma_bf16(float* d, const uint32_t* a,
                                         const uint32_t* b) {
    asm volatile(
        "mma.sync.aligned.m16n8k16.row.col.f32.bf16.bf16.f32 "
        "{%0,%1,%2,%3}, {%4,%5,%6,%7}, {%8,%9}, {%0,%1,%2,%3};"
        : "+f"(d[0]), "+f"(d[1]), "+f"(d[2]), "+f"(d[3])
        : "r"(a[0]), "r"(a[1]), "r"(a[2]), "r"(a[3]), "r"(b[0]), "r"(b[1]));
}
__device__ __forceinline__ void stcs2(float* p, float2 v) {
    asm volatile("st.global.cs.v2.f32 [%0], {%1, %2};"
                 :: "l"(p), "f"(v.x), "f"(v.y) : "memory");
}

// ---------------- kernel 1: a = (m @ W_in[0:32]^T + b_in)*mask, split bf16 --
// grid 24, block 512: 16 rows each, thread = (row rl, h).
__global__ __launch_bounds__(512) void k1_projA(
        const float* __restrict__ m,
        const float* __restrict__ W_in,
        const float* __restrict__ b_in,
        const float* __restrict__ op_mask)
{
    __shared__ float m_s[16 * 128];        // [row][k]
    __shared__ float Wa_s[128 * 33];       // [k][h], stride 33 (conflict-free)
    const int tid = threadIdx.x;
    const int n0  = blockIdx.x * 16;

    {   // m rows: 512 float4
        int row = tid >> 5, q = tid & 31;
        ((float4*)(m_s + row * 128))[q] =
            ((const float4*)m)[(size_t)(n0 + row) * 32 + q];
    }
    #pragma unroll
    for (int i = 0; i < 8; ++i) {          // W_in rows 0..31 (a-half), 4096 f
        int e = tid + i * 512;
        int h = e >> 7, k = e & 127;
        Wa_s[k * 33 + h] = W_in[e];
    }
    __syncthreads();

    const int rl = tid >> 5;               // 0..15
    const int h  = tid & 31;               // 0..31
    float acc0 = 0.f, acc1 = 0.f;
    #pragma unroll 8
    for (int k = 0; k < 128; k += 2) {
        acc0 += m_s[rl * 128 + k]     * Wa_s[k * 33 + h];
        acc1 += m_s[rl * 128 + k + 1] * Wa_s[(k + 1) * 33 + h];
    }
    float v = (acc0 + acc1 + b_in[h]) * op_mask[0];
    __nv_bfloat16 ah = __float2bfloat16(v);
    __nv_bfloat16 al = __float2bfloat16(v - __bfloat162float(ah));
    g_Ah[(n0 + rl) * DHID + h] = ah;
    g_Al[(n0 + rl) * DHID + h] = al;
}

// ---------------- kernel 2: self-contained b + C -----------------------------
// phase1: b[j,y] = m[j]·W_in[32+y] + b_in[32+y], *mask (16 j per block)
// phase2: C[n=j*64+p][x] = sum_y b[j,y]*W_out[p,32x+y], split bf16, [N][K] layout
__global__ __launch_bounds__(256) void k2_makeC(
        const float* __restrict__ m,
        const float* __restrict__ W_in,
        const float* __restrict__ b_in,
        const float* __restrict__ op_mask,
        const float* __restrict__ W_out)
{
    __shared__ float S[256 * 33];          // 8448 floats, reused across phases
    __shared__ float b_s[16 * 32];
    const int tid = threadIdx.x;
    const int rt  = blockIdx.x;            // rows rt*256..+255 (row = p*32+x)
    const int j0  = blockIdx.y * 16;

    // ---- phase 1: compute b for rows j0..j0+15 ----
    float* m_s  = S;                       // [16][128] = 2048
    float* Wb_s = S + 2048;                // [128][33] = 4224
    #pragma unroll
    for (int i = 0; i < 2; ++i) {
        int e = tid + i * 256;             // 512 float4
        int row = e >> 5, q = e & 31;
        ((float4*)(m_s + row * 128))[q] =
            ((const float4*)m)[(size_t)(j0 + row) * 32 + q];
    }
    #pragma unroll
    for (int i = 0; i < 16; ++i) {         // W_in rows 32..63
        int e = tid + i * 256;
        int hy = e >> 7, k = e & 127;
        Wb_s[k * 33 + hy] = W_in[4096 + e];
    }
    __syncthreads();

    const float opm = op_mask[0];
    #pragma unroll
    for (int half = 0; half < 2; ++half) {
        int t = tid + half * 256;
        int j = t >> 5, y = t & 31;
        float a0 = 0.f, a1 = 0.f;
        #pragma unroll 8
        for (int k = 0; k < 128; k += 2) {
            a0 += m_s[j * 128 + k]     * Wb_s[k * 33 + y];
            a1 += m_s[j * 128 + k + 1] * Wb_s[(k + 1) * 33 + y];
        }
        b_s[j * 32 + y] = (a0 + a1 + b_in[32 + y]) * opm;
    }
    __syncthreads();

    // ---- phase 2: C tile ----
    float* W_t = S;                        // [256][33] = 8448
    #pragma unroll
    for (int i = 0; i < 32; ++i) {
        int e = tid + i * 256;
        W_t[(e >> 5) * 33 + (e & 31)] = W_out[rt * 8192 + e];
    }
    __syncthreads();

    float wreg[32];
    #pragma unroll
    for (int y = 0; y < 32; ++y) wreg[y] = W_t[tid * 33 + y];

    float acc[16];
    #pragma unroll
    for (int j = 0; j < 16; ++j) acc[j] = 0.f;
    #pragma unroll
    for (int y = 0; y < 32; ++y) {
        float w = wreg[y];
        #pragma unroll
        for (int j = 0; j < 16; ++j) acc[j] += w * b_s[j * 32 + y];
    }

    const int row = rt * 256 + tid;        // row = p*32 + x
    #pragma unroll
    for (int j = 0; j < 16; ++j) {
        float c = acc[j];
        __nv_bfloat16 ch = __float2bfloat16(c);
        __nv_bfloat16 cl = __float2bfloat16(c - __bfloat162float(ch));
        int idx = (j0 + j) * 2048 + row;   // = n*32 + x
        g_Ch[idx] = ch;
        g_Cl[idx] = cl;
    }
}

// ---------------- kernel 3: Z = A @ C^T via mma.sync, M128 x N256, K32 -----
#define SROW 40                             // bf16 row stride (80 B)
#define OAH   0
#define OAL   (OAH + 128 * SROW * 2)        // 10240
#define OBH   (OAL + 128 * SROW * 2)        // 20480
#define OBL   (OBH + 256 * SROW * 2)        // 40960
#define OBIAS (OBL + 256 * SROW * 2)        // 61440
#define SMEM_K3 (OBIAS + 256)               // 61696

__global__ __launch_bounds__(512, 1) void k3_gemm_mma(
        const float* __restrict__ b_out,
        const float* __restrict__ op_norm,
        float* __restrict__ out)
{
    extern __shared__ char smem[];
    __nv_bfloat16* sAh = (__nv_bfloat16*)(smem + OAH);
    __nv_bfloat16* sAl = (__nv_bfloat16*)(smem + OAL);
    __nv_bfloat16* sBh = (__nv_bfloat16*)(smem + OBH);
    __nv_bfloat16* sBl = (__nv_bfloat16*)(smem + OBL);
    float*       s_bias = (float*)(smem + OBIAS);

    const int tid  = threadIdx.x;
    const int wid  = tid >> 5;
    const int lane = tid & 31;
    const int n0   = blockIdx.x * 256;
    const int m0   = blockIdx.y * 128;

    {   // A tile: 128 rows x 4 chunks
        int row = tid >> 2, ch = tid & 3;
        size_t ga = (size_t)(m0 + row) * DHID + ch * 8;
        int d = row * SROW + ch * 8;
        *(uint4*)(sAh + d) = *(const uint4*)(g_Ah + ga);
        *(uint4*)(sAl + d) = *(const uint4*)(g_Al + ga);
    }
    #pragma unroll
    for (int i = 0; i < 2; ++i) {          // B tile: 256 rows x 4 chunks
        int e = tid + i * 512;
        int row = e >> 2, ch = e & 3;
        size_t gb = (size_t)(n0 + row) * DHID + ch * 8;
        int d = row * SROW + ch * 8;
        *(uint4*)(sBh + d) = *(const uint4*)(g_Ch + gb);
        *(uint4*)(sBl + d) = *(const uint4*)(g_Cl + gb);
    }
    if (tid < 64) s_bias[tid] = b_out[tid];
    __syncthreads();

    const int warp_m = wid & 3;            // 32 rows
    const int warp_n = wid >> 2;           // 64 cols

    const uint32_t ah_b = smem_u32(sAh);
    const uint32_t al_b = smem_u32(sAl);
    const uint32_t bh_b = smem_u32(sBh);
    const uint32_t bl_b = smem_u32(sBl);

    float D[2][8][4];
    #pragma unroll
    for (int mf = 0; mf < 2; ++mf)
        #pragma unroll
        for (int nf = 0; nf < 8; ++nf)
            #pragma unroll
            for (int q = 0; q < 4; ++q) D[mf][nf][q] = 0.f;

    #pragma unroll
    for (int ks = 0; ks < 2; ++ks) {
        const int kk = ks * 16;
        uint32_t Ah[2][4], Al[2][4];
        #pragma unroll
        for (int mf = 0; mf < 2; ++mf) {
            int row = warp_m * 32 + mf * 16 + (lane & 15);
            int col = kk + (lane >> 4) * 8;
            uint32_t off = row * (SROW * 2) + col * 2;
            ldsm_x4(Ah[mf], ah_b + off);
            ldsm_x4(Al[mf], al_b + off);
        }
        // B: x4 covers two adjacent 8-col groups (nf=2g, 2g+1)
        int brow_c = (lane & 7) + ((lane >> 4) & 1) * 8;
        int bcol   = kk + (lane & 8);
        #pragma unroll
        for (int g = 0; g < 4; ++g) {
            int brow = warp_n * 64 + g * 16 + brow_c;
            uint32_t off = brow * (SROW * 2) + bcol * 2;
            uint32_t Bh[4], Bl[4];
            ldsm_x4(Bh, bh_b + off);
            ldsm_x4(Bl, bl_b + off);
            #pragma unroll
            for (int mf = 0; mf < 2; ++mf) {
                mma_bf16(D[mf][2 * g],     Ah[mf], Bh);
                mma_bf16(D[mf][2 * g],     Ah[mf], Bl);
                mma_bf16(D[mf][2 * g],     Al[mf], Bh);
                mma_bf16(D[mf][2 * g + 1], Ah[mf], Bh + 2);
                mma_bf16(D[mf][2 * g + 1], Ah[mf], Bl + 2);
                mma_bf16(D[mf][2 * g + 1], Al[mf], Bh + 2);
            }
        }
    }

    // ---- epilogue: streaming stores (write-once output) ----
    const float opn = op_norm[0];
    const int rgrp  = lane >> 2;
    const int cpair = (lane & 3) * 2;
    #pragma unroll
    for (int mf = 0; mf < 2; ++mf) {
        #pragma unroll
        for (int nf = 0; nf < 8; ++nf) {
            int ncl  = nf * 8 + cpair;                 // 0..63 within 64-col warp tile
            int col  = n0 + warp_n * 64 + ncl;
            float b0 = s_bias[ncl];
            float b1 = s_bias[ncl + 1];
            int r0 = m0 + warp_m * 32 + mf * 16 + rgrp;
            stcs2(out + (size_t)r0 * NCOL + col,
                  make_float2((D[mf][nf][0] + b0) * opn, (D[mf][nf][1] + b1) * opn));
            stcs2(out + (size_t)(r0 + 8) * NCOL + col,
                  make_float2((D[mf][nf][2] + b0) * opn, (D[mf][nf][3] + b1) * opn));
        }
    }
}

// ---------------- launch ---------------------------------------------------
extern "C" void kernel_launch(void* const* d_in, const int* in_sizes, int n_in,
                              void* d_out, int out_size)
{
    (void)in_sizes; (void)n_in; (void)out_size;
    const float* m       = (const float*)d_in[0];
    /* d_in[1] = nlist: unused by the reference */
    const float* op_mask = (const float*)d_in[2];
    const float* op_norm = (const float*)d_in[3];
    const float* W_in    = (const float*)d_in[4];
    const float* b_in    = (const float*)d_in[5];
    const float* W_out   = (const float*)d_in[6];
    const float* b_out   = (const float*)d_in[7];
    float* out = (float*)d_out;

    cudaFuncSetAttribute(k3_gemm_mma,
                         cudaFuncAttributeMaxDynamicSharedMemorySize, SMEM_K3);

    k1_projA   <<<24, 512>>>(m, W_in, b_in, op_mask);
    k2_makeC   <<<dim3(8, 24), 256>>>(m, W_in, b_in, op_mask, W_out);
    k3_gemm_mma<<<dim3(96, 3), 512, SMEM_K3>>>(b_out, op_norm, out);
}

// round 6
// speedup vs baseline: 1.1847x; 1.1847x over previous
#include <cuda_runtime.h>
#include <cuda_fp16.h>
#include <cstdint>

#define NLOC  384
#define DHID  32
#define DPAIR 64
#define NCOL  (NLOC * DPAIR)   // 24576

// ---------------- scratch (static device globals; no allocations) ----------
__device__ __align__(16) __half g_Ah[NLOC * DHID];  // a fp16      [384][32]
__device__ __align__(16) __half g_Ch[NCOL * DHID];  // C hi fp16   [24576][32]
__device__ __align__(16) __half g_Cl[NCOL * DHID];  // C lo fp16   [24576][32]

// ---------------- mma.sync / ldmatrix helpers -------------------------------
__device__ __forceinline__ uint32_t smem_u32(const void* p) {
    uint32_t a;
    asm("{ .reg .u64 t; cvta.to.shared.u64 t, %1; cvt.u32.u64 %0, t; }"
        : "=r"(a) : "l"(p));
    return a;
}
__device__ __forceinline__ void ldsm_x4(uint32_t* r, uint32_t addr) {
    asm volatile("ldmatrix.sync.aligned.m8n8.x4.shared.b16 {%0,%1,%2,%3}, [%4];"
                 : "=r"(r[0]), "=r"(r[1]), "=r"(r[2]), "=r"(r[3]) : "r"(addr));
}
__device__ __forceinline__ void mma_f16(float* d, const uint32_t* a,
                                        const uint32_t* b) {
    asm volatile(
        "mma.sync.aligned.m16n8k16.row.col.f32.f16.f16.f32 "
        "{%0,%1,%2,%3}, {%4,%5,%6,%7}, {%8,%9}, {%0,%1,%2,%3};"
        : "+f"(d[0]), "+f"(d[1]), "+f"(d[2]), "+f"(d[3])
        : "r"(a[0]), "r"(a[1]), "r"(a[2]), "r"(a[3]), "r"(b[0]), "r"(b[1]));
}
__device__ __forceinline__ void stcs2(float* p, float2 v) {
    asm volatile("st.global.cs.v2.f32 [%0], {%1, %2};"
                 :: "l"(p), "f"(v.x), "f"(v.y) : "memory");
}

// ---------------- kernel 12: fused A-projection + C-build -------------------
// blocks 0..191  : C role. rt = bid&7 (256-row W_out slice), j0 = (bid>>3)*16.
//   phase1: b[j,y] = m[j]·W_in[32+y] + b_in[32+y], *mask
//   phase2: C[n=j*64+p][x] = sum_y b[j,y]*W_out[p,32x+y] -> fp16 hi/lo
// blocks 192..215: A role. n0 = (bid-192)*16. a = m@W_in[0:32]^T + b_in, fp16.
__global__ __launch_bounds__(256) void k12(
        const float* __restrict__ m,
        const float* __restrict__ W_in,
        const float* __restrict__ b_in,
        const float* __restrict__ op_mask,
        const float* __restrict__ W_out)
{
    __shared__ float S[256 * 33];          // 8448 floats, role/phase reused
    __shared__ float b_s[16 * 32];
    const int tid = threadIdx.x;
    const int bid = blockIdx.x;

    if (bid >= 192) {
        // ---------------- A role ----------------
        const int n0 = (bid - 192) * 16;
        float* m_s  = S;                   // [16][128]
        float* Wa_s = S + 2048;            // [128][33]
        #pragma unroll
        for (int i = 0; i < 2; ++i) {
            int e = tid + i * 256;         // 512 float4
            int row = e >> 5, q = e & 31;
            ((float4*)(m_s + row * 128))[q] =
                ((const float4*)m)[(size_t)(n0 + row) * 32 + q];
        }
        #pragma unroll
        for (int i = 0; i < 16; ++i) {     // W_in rows 0..31
            int e = tid + i * 256;
            Wa_s[(e & 127) * 33 + (e >> 7)] = W_in[e];
        }
        __syncthreads();

        const float opm = op_mask[0];
        #pragma unroll
        for (int half = 0; half < 2; ++half) {
            int t = tid + half * 256;
            int rl = t >> 5, h = t & 31;
            float a0 = 0.f, a1 = 0.f;
            #pragma unroll 8
            for (int k = 0; k < 128; k += 2) {
                a0 += m_s[rl * 128 + k]     * Wa_s[k * 33 + h];
                a1 += m_s[rl * 128 + k + 1] * Wa_s[(k + 1) * 33 + h];
            }
            float v = (a0 + a1 + b_in[h]) * opm;
            g_Ah[(n0 + rl) * DHID + h] = __float2half_rn(v);
        }
        return;
    }

    // ---------------- C role ----------------
    const int rt = bid & 7;                // rows rt*256..+255 (row = p*32+x)
    const int j0 = (bid >> 3) * 16;

    // phase 1: b for rows j0..j0+15
    float* m_s  = S;                       // [16][128]
    float* Wb_s = S + 2048;                // [128][33]
    #pragma unroll
    for (int i = 0; i < 2; ++i) {
        int e = tid + i * 256;
        int row = e >> 5, q = e & 31;
        ((float4*)(m_s + row * 128))[q] =
            ((const float4*)m)[(size_t)(j0 + row) * 32 + q];
    }
    #pragma unroll
    for (int i = 0; i < 16; ++i) {         // W_in rows 32..63
        int e = tid + i * 256;
        Wb_s[(e & 127) * 33 + (e >> 7)] = W_in[4096 + e];
    }
    __syncthreads();

    const float opm = op_mask[0];
    #pragma unroll
    for (int half = 0; half < 2; ++half) {
        int t = tid + half * 256;
        int j = t >> 5, y = t & 31;
        float a0 = 0.f, a1 = 0.f;
        #pragma unroll 8
        for (int k = 0; k < 128; k += 2) {
            a0 += m_s[j * 128 + k]     * Wb_s[k * 33 + y];
            a1 += m_s[j * 128 + k + 1] * Wb_s[(k + 1) * 33 + y];
        }
        b_s[j * 32 + y] = (a0 + a1 + b_in[32 + y]) * opm;
    }
    __syncthreads();

    // phase 2: C tile
    float* W_t = S;                        // [256][33]
    #pragma unroll
    for (int i = 0; i < 32; ++i) {
        int e = tid + i * 256;
        W_t[(e >> 5) * 33 + (e & 31)] = W_out[rt * 8192 + e];
    }
    __syncthreads();

    float wreg[32];
    #pragma unroll
    for (int y = 0; y < 32; ++y) wreg[y] = W_t[tid * 33 + y];

    float acc[16];
    #pragma unroll
    for (int j = 0; j < 16; ++j) acc[j] = 0.f;
    #pragma unroll
    for (int y = 0; y < 32; ++y) {
        float w = wreg[y];
        #pragma unroll
        for (int j = 0; j < 16; ++j) acc[j] += w * b_s[j * 32 + y];
    }

    const int row = rt * 256 + tid;        // row = p*32 + x
    #pragma unroll
    for (int j = 0; j < 16; ++j) {
        float c = acc[j];
        __half ch = __float2half_rn(c);
        __half cl = __float2half_rn(c - __half2float(ch));
        int idx = (j0 + j) * 2048 + row;   // = n*32 + x
        g_Ch[idx] = ch;
        g_Cl[idx] = cl;
    }
}

// ---------------- kernel 3: Z = A @ C^T via mma.sync fp16, 2-pass split ----
// Block M=128, N=128, K=32. 8 warps as 4(M) x 2(N). 256 threads.
// D = A @ Ch + A @ Cl  (A plain fp16; error ~2^-12, well under 1e-3)
#define SROW 40
__global__ __launch_bounds__(256) void k3_gemm_mma(
        const float* __restrict__ b_out,
        const float* __restrict__ op_norm,
        float* __restrict__ out)
{
    __shared__ __align__(16) __half sA [128 * SROW];
    __shared__ __align__(16) __half sBh[128 * SROW];
    __shared__ __align__(16) __half sBl[128 * SROW];
    __shared__ float s_bias[64];

    const int tid  = threadIdx.x;
    const int wid  = tid >> 5;
    const int lane = tid & 31;
    const int n0   = blockIdx.x * 128;
    const int m0   = blockIdx.y * 128;

    #pragma unroll
    for (int i = 0; i < 2; ++i) {
        int e = tid + i * 256;            // 0..511 : 128 rows x 4 chunks
        int row = e >> 2, ch = e & 3;
        size_t ga = (size_t)(m0 + row) * DHID + ch * 8;
        size_t gb = (size_t)(n0 + row) * DHID + ch * 8;
        int d = row * SROW + ch * 8;
        *(uint4*)(sA  + d) = *(const uint4*)(g_Ah + ga);
        *(uint4*)(sBh + d) = *(const uint4*)(g_Ch + gb);
        *(uint4*)(sBl + d) = *(const uint4*)(g_Cl + gb);
    }
    if (tid < 64) s_bias[tid] = b_out[tid];
    __syncthreads();

    const int warp_m = wid & 3;            // 32 rows
    const int warp_n = wid >> 2;           // 64 cols

    const uint32_t a_b  = smem_u32(sA);
    const uint32_t bh_b = smem_u32(sBh);
    const uint32_t bl_b = smem_u32(sBl);

    float D[2][8][4];
    #pragma unroll
    for (int mf = 0; mf < 2; ++mf)
        #pragma unroll
        for (int nf = 0; nf < 8; ++nf)
            #pragma unroll
            for (int q = 0; q < 4; ++q) D[mf][nf][q] = 0.f;

    #pragma unroll
    for (int ks = 0; ks < 2; ++ks) {
        const int kk = ks * 16;
        uint32_t A[2][4];
        #pragma unroll
        for (int mf = 0; mf < 2; ++mf) {
            int row = warp_m * 32 + mf * 16 + (lane & 15);
            int col = kk + (lane >> 4) * 8;
            ldsm_x4(A[mf], a_b + row * (SROW * 2) + col * 2);
        }
        // B: each ldsm_x4 covers two adjacent 8-col n-groups of one k-half
        int brow_c = (lane & 7) + ((lane >> 4) & 1) * 8;
        int bcol   = kk + (lane & 8);
        #pragma unroll
        for (int g = 0; g < 4; ++g) {
            int brow = warp_n * 64 + g * 16 + brow_c;
            uint32_t off = brow * (SROW * 2) + bcol * 2;
            uint32_t Bh[4], Bl[4];
            ldsm_x4(Bh, bh_b + off);
            ldsm_x4(Bl, bl_b + off);
            #pragma unroll
            for (int mf = 0; mf < 2; ++mf) {
                mma_f16(D[mf][2 * g],     A[mf], Bh);
                mma_f16(D[mf][2 * g],     A[mf], Bl);
                mma_f16(D[mf][2 * g + 1], A[mf], Bh + 2);
                mma_f16(D[mf][2 * g + 1], A[mf], Bl + 2);
            }
        }
    }

    // ---- epilogue: streaming stores (write-once output) ----
    const float opn = op_norm[0];
    const int rgrp  = lane >> 2;
    const int cpair = (lane & 3) * 2;
    #pragma unroll
    for (int mf = 0; mf < 2; ++mf) {
        #pragma unroll
        for (int nf = 0; nf < 8; ++nf) {
            int ncl  = nf * 8 + cpair;             // 0..63 == p index
            int col  = n0 + warp_n * 64 + ncl;
            float b0 = s_bias[ncl];
            float b1 = s_bias[ncl + 1];
            int r0 = m0 + warp_m * 32 + mf * 16 + rgrp;
            stcs2(out + (size_t)r0 * NCOL + col,
                  make_float2((D[mf][nf][0] + b0) * opn, (D[mf][nf][1] + b1) * opn));
            stcs2(out + (size_t)(r0 + 8) * NCOL + col,
                  make_float2((D[mf][nf][2] + b0) * opn, (D[mf][nf][3] + b1) * opn));
        }
    }
}

// ---------------- launch ---------------------------------------------------
extern "C" void kernel_launch(void* const* d_in, const int* in_sizes, int n_in,
                              void* d_out, int out_size)
{
    (void)in_sizes; (void)n_in; (void)out_size;
    const float* m       = (const float*)d_in[0];
    /* d_in[1] = nlist: unused by the reference */
    const float* op_mask = (const float*)d_in[2];
    const float* op_norm = (const float*)d_in[3];
    const float* W_in    = (const float*)d_in[4];
    const float* b_in    = (const float*)d_in[5];
    const float* W_out   = (const float*)d_in[6];
    const float* b_out   = (const float*)d_in[7];
    float* out = (float*)d_out;

    k12        <<<216, 256>>>(m, W_in, b_in, op_mask, W_out);
    k3_gemm_mma<<<dim3(192, 3), 256>>>(b_out, op_norm, out);
}